// round 12
// baseline (speedup 1.0000x reference)
#include <cuda_runtime.h>

#define BB    2048
#define TR    2080   // row length of transposed qx (floats); rows zero-padded
#define TROUT 2048   // row length of transposed output

__device__ float g_qxT[(size_t)BB * TR];
__device__ float g_outT[(size_t)BB * TROUT];   // stores raw tanh values

// ---------------------------------------------------------------------------
// Kernel A: FIR pre-pass (unchanged from round 8)
// ---------------------------------------------------------------------------
__global__ void __launch_bounds__(128) fir_kernel(
    const float* __restrict__ cur,
    const float* __restrict__ a,
    const float* __restrict__ b_act,
    const float* __restrict__ max_cur,
    int T)
{
    __shared__ float sm[191][64];
    const int li = threadIdx.x & 63;
    const int th = threadIdx.x >> 6;
    const int i  = blockIdx.x * 64 + li;
    const int t0 = blockIdx.y * 128;

    float areg[64];
#pragma unroll
    for (int k = 0; k < 64; ++k) areg[k] = __ldg(&a[k]);
    const float bact   = __ldg(&b_act[0]);
    const float inv_mc = 1.0f / __ldg(&max_cur[0]);

#pragma unroll 4
    for (int rr = th; rr < 191; rr += 2) {
        int s = t0 - 63 + rr;
        sm[rr][li] = (s >= 0 && s < T) ? __ldg(&cur[(size_t)s * BB + i]) : 0.0f;
    }
    __syncthreads();

    float* myrow = g_qxT + (size_t)i * TR;
    const int tb = th * 64;

#pragma unroll 1
    for (int g = 0; g < 8; ++g) {
        const int tt = tb + g * 8;
        float acc[8];
#pragma unroll
        for (int o = 0; o < 8; ++o) acc[o] = 0.0f;
#pragma unroll
        for (int rr = 0; rr < 71; ++rr) {
            float v = sm[tt + rr][li];
#pragma unroll
            for (int o = 0; o < 8; ++o)
                if (rr >= o && rr <= o + 63)
                    acc[o] = fmaf(areg[rr - o], v, acc[o]);
        }
        const int t = t0 + tt;
        float r0 = (acc[0] - bact) * inv_mc, r1 = (acc[1] - bact) * inv_mc;
        float r2 = (acc[2] - bact) * inv_mc, r3 = (acc[3] - bact) * inv_mc;
        float r4 = (acc[4] - bact) * inv_mc, r5 = (acc[5] - bact) * inv_mc;
        float r6 = (acc[6] - bact) * inv_mc, r7 = (acc[7] - bact) * inv_mc;
        if (t + 7 < T) {
            *(float4*)(myrow + t)     = make_float4(r0, r1, r2, r3);
            *(float4*)(myrow + t + 4) = make_float4(r4, r5, r6, r7);
        } else {
            if (t + 0 < T) myrow[t + 0] = r0;
            if (t + 1 < T) myrow[t + 1] = r1;
            if (t + 2 < T) myrow[t + 2] = r2;
            if (t + 3 < T) myrow[t + 3] = r3;
            if (t + 4 < T) myrow[t + 4] = r4;
            if (t + 5 < T) myrow[t + 5] = r5;
            if (t + 6 < T) myrow[t + 6] = r6;
            if (t + 7 < T) myrow[t + 7] = r7;
        }
    }
}

// ---------------------------------------------------------------------------
// Kernel B: 8 lanes/element, rotated taps j = 8r+4..8r+11 (weights 0 for
// j>64), taps 1..3 local to lane0. Depth-2 broadcast delay: scatter at step
// s consumes tbPrev2 = th(s-2), whose shfl resolved a full step earlier ->
// ptxas can interleave all off-chain work into the serial chain's stalls.
// Lane0 y-pipeline (target sigma+2): release adds W3L*th(sigma-1) and
// W2L*th(sigma); consume adds W1L*th(sigma+1) (single on-chain fma).
// g_outT stores raw th; mfr applied in tr_kernel.
// ---------------------------------------------------------------------------
#define STEP(p, qv2) { \
    /* serial chain */ \
    float xx_ = fmaf(W1L, thPrev, yq[(p)&1]); \
    float u_  = xx_ * xx_; \
    float s1_ = fmaf(c1, xx_, c0); \
    float s2_ = fmaf(c3, xx_, c2); \
    float pv_ = fmaf(u_, s2_, s1_); \
    float pr_ = fmaxf(pv_, 0.0f); \
    float th_; asm("tanh.approx.f32 %0, %1;" : "=f"(th_) : "f"(pr_)); \
    fbv[(p)&7] = th_; \
    float tb_ = __shfl_sync(0xffffffffu, th_, 0, 8); \
    /* deferred seed (hUPrev: shfl_down from last step) */ \
    R[((p)+7)&7] = hUPrev * u7; \
    /* scatter with 2-step-old broadcast (fully resolved) */ \
    R[((p)+0)&7] = fmaf(W[0], tbPrev2, R[((p)+0)&7]); \
    R[((p)+1)&7] = fmaf(W[1], tbPrev2, R[((p)+1)&7]); \
    R[((p)+2)&7] = fmaf(W[2], tbPrev2, R[((p)+2)&7]); \
    R[((p)+3)&7] = fmaf(W[3], tbPrev2, R[((p)+3)&7]); \
    R[((p)+4)&7] = fmaf(W[4], tbPrev2, R[((p)+4)&7]); \
    R[((p)+5)&7] = fmaf(W[5], tbPrev2, R[((p)+5)&7]); \
    R[((p)+6)&7] = fmaf(W[6], tbPrev2, R[((p)+6)&7]); \
    R[((p)+7)&7] = fmaf(W[7], tbPrev2, R[((p)+7)&7]); \
    /* release + hand-off + y-pipeline update */ \
    float valRel_ = R[(p)&7]; \
    float hU_ = __shfl_down_sync(0xffffffffu, valRel_, 1, 8); \
    float y0_ = fmaf(W3L, thPrev, valRel_); \
    float y_  = fmaf(W2L, th_, y0_); \
    yq[(p)&1] = y_ + (qv2); \
    thPrev = th_; \
    tbPrev2 = tbPrev; \
    tbPrev  = tb_; \
    hUPrev  = hU_; \
}

#define S8(qa, qb, nx) \
    STEP(0,(qa).z) STEP(1,(qa).w) STEP(2,(qb).x) STEP(3,(qb).y) \
    STEP(4,(qb).z) STEP(5,(qb).w) STEP(6,(nx).x) STEP(7,(nx).y)

#define EMIT() if (r == 0) { \
        *(float4*)(optr + 0) = make_float4(fbv[0], fbv[1], fbv[2], fbv[3]); \
        *(float4*)(optr + 4) = make_float4(fbv[4], fbv[5], fbv[6], fbv[7]); \
    } \
    optr += 8;

__global__ void __launch_bounds__(128) rec_kernel(
    const float* __restrict__ b_lag,
    const float* __restrict__ poly_coeff,
    const float* __restrict__ max_cur,
    int T)
{
    const int tid = threadIdx.x;
    const int r   = tid & 7;
    const int e   = blockIdx.x * 16 + (tid >> 3);

    const float inv_mc = 1.0f / __ldg(&max_cur[0]);
    float c0 = __ldg(&poly_coeff[0]); c0 *= c0;
    float c1 = __ldg(&poly_coeff[1]); c1 *= c1;
    float c2 = __ldg(&poly_coeff[2]); c2 *= c2;
    float c3 = __ldg(&poly_coeff[3]); c3 *= c3;
    const float cw = 1000.0f * inv_mc;   // tanh values scattered raw; mfr folded here

    // NOTE: feedback uses f = mfr*th; we scatter th, so weights absorb mfr? No:
    // here weights must include mfr because the scattered value is th, and the
    // reference scatters f = mfr*th. Keep cwm = cw * mfr.
    // mfr only needed for weights, not for the output scaling (done in tr).
    // (loaded below)
    return; // placeholder never reached; real body follows in rec_kernel2
}

// Real recurrence kernel (the one above is unused; kept minimal to avoid
// accidental launch). See kernel_launch: we launch rec_kernel2.
__global__ void __launch_bounds__(128) rec_kernel2(
    const float* __restrict__ b_lag,
    const float* __restrict__ poly_coeff,
    const float* __restrict__ max_cur,
    const float* __restrict__ max_fr,
    int T)
{
    const int tid = threadIdx.x;
    const int r   = tid & 7;
    const int e   = blockIdx.x * 16 + (tid >> 3);

    const float inv_mc = 1.0f / __ldg(&max_cur[0]);
    const float mfr    = __ldg(&max_fr[0]);
    float c0 = __ldg(&poly_coeff[0]); c0 *= c0;
    float c1 = __ldg(&poly_coeff[1]); c1 *= c1;
    float c2 = __ldg(&poly_coeff[2]); c2 *= c2;
    float c3 = __ldg(&poly_coeff[3]); c3 *= c3;
    const float cwm = 1000.0f * inv_mc * mfr;   // weights absorb mfr (we scatter th)

    // lane r owns taps j = 8r+4+k (k=0..7); W[k] = cwm*b_lag[64-j], 0 if j>64
    float W[8];
#pragma unroll
    for (int k = 0; k < 8; ++k) {
        int j = 8 * r + 4 + k;
        W[k] = (j <= 64) ? cwm * __ldg(&b_lag[64 - j]) : 0.0f;
    }
    // lane0-only local taps 1,2,3
    const float W1L = (r == 0) ? cwm * __ldg(&b_lag[63]) : 0.0f;
    const float W2L = (r == 0) ? cwm * __ldg(&b_lag[62]) : 0.0f;
    const float W3L = (r == 0) ? cwm * __ldg(&b_lag[61]) : 0.0f;
    const float u7  = (r == 7) ? 0.0f : 1.0f;

    float R[8];
#pragma unroll
    for (int k = 0; k < 8; ++k) R[k] = 0.0f;
    float fbv[8];
    float thPrev = 0.0f, tbPrev = 0.0f, tbPrev2 = 0.0f, hUPrev = 0.0f;

    const float4* qrow = (const float4*)(g_qxT + (size_t)e * TR);
    float* optr = g_outT + (size_t)e * TROUT;

    float4 qa = __ldg(qrow + 0), qb = __ldg(qrow + 1);
    float yq[2] = { qa.x, qa.y };   // y=0 initially, q pre-added

    const int nfull = T >> 3;
    const int npair = nfull >> 1;
    for (int m = 0; m < npair; ++m) {
        float4 na = __ldg(qrow + (size_t)(4 * m) + 2);
        float4 nb = __ldg(qrow + (size_t)(4 * m) + 3);
        S8(qa, qb, na)
        EMIT()
        qa = __ldg(qrow + (size_t)(4 * m) + 4);
        qb = __ldg(qrow + (size_t)(4 * m) + 5);
        S8(na, nb, qa)
        EMIT()
    }
    if (nfull & 1) {
        float4 nq = __ldg(qrow + (size_t)(2 * nfull));   // zero-padded, safe
        S8(qa, qb, nq)
        EMIT()
    }

    // ---- generic tail (T mod 8 steps; empty for T=2000) ----
    const int t0tail = nfull * 8;
    const int tail   = T - t0tail;
    if (tail > 0) {
#pragma unroll 1
        for (int tt = 0; tt < tail; ++tt) {
            int t = t0tail + tt;
            int p = t & 7;
            float xx = fmaf(W1L, thPrev, yq[p & 1]);
            float u_  = xx * xx;
            float s1_ = fmaf(c1, xx, c0);
            float s2_ = fmaf(c3, xx, c2);
            float pv  = fmaf(u_, s2_, s1_);
            float pr  = fmaxf(pv, 0.0f);
            float th; asm("tanh.approx.f32 %0, %1;" : "=f"(th) : "f"(pr));
            if (r == 0) g_outT[(size_t)e * TROUT + t] = th;
            float tbn = __shfl_sync(0xffffffffu, th, 0, 8);
            R[(p + 7) & 7] = hUPrev * u7;
#pragma unroll 1
            for (int k = 0; k < 8; ++k)
                R[(p + k) & 7] = fmaf(W[k], tbPrev2, R[(p + k) & 7]);
            float valRel = R[p];
            float hU = __shfl_down_sync(0xffffffffu, valRel, 1, 8);
            float y0 = fmaf(W3L, thPrev, valRel);
            float y_ = fmaf(W2L, th, y0);
            yq[p & 1] = y_ + __ldg(g_qxT + (size_t)e * TR + (t + 2)); // padded
            thPrev = th; tbPrev2 = tbPrev; tbPrev = tbn; hUPrev = hU;
        }
    }
}

// ---------------------------------------------------------------------------
// Kernel C: transpose g_outT[e][t] -> out[t][e], scaling by mfr.
// ---------------------------------------------------------------------------
__global__ void __launch_bounds__(256) tr_kernel(
    float* __restrict__ out, const float* __restrict__ max_fr, int T)
{
    __shared__ float tile[32][33];
    const int tx = threadIdx.x, ty = threadIdx.y;
    const int e0 = blockIdx.x * 32;
    const int t0 = blockIdx.y * 32;
    const float mfr = __ldg(&max_fr[0]);

#pragma unroll
    for (int j = 0; j < 4; ++j) {
        int e = e0 + ty + 8 * j;
        int t = t0 + tx;
        tile[ty + 8 * j][tx] = (t < T) ? mfr * g_outT[(size_t)e * TROUT + t] : 0.0f;
    }
    __syncthreads();
#pragma unroll
    for (int j = 0; j < 4; ++j) {
        int t = t0 + ty + 8 * j;
        if (t < T) out[(size_t)t * BB + e0 + tx] = tile[tx][ty + 8 * j];
    }
}

// ---------------------------------------------------------------------------
extern "C" void kernel_launch(void* const* d_in, const int* in_sizes, int n_in,
                              void* d_out, int out_size)
{
    const float* currents = (const float*)d_in[0];
    const float* a        = (const float*)d_in[1];
    const float* b_lag    = (const float*)d_in[2];
    const float* poly     = (const float*)d_in[3];
    const float* b_act    = (const float*)d_in[4];
    const float* max_cur  = (const float*)d_in[5];
    const float* max_fr   = (const float*)d_in[6];
    float* out = (float*)d_out;

    const int T = in_sizes[0] / BB;   // 2000

    dim3 gA(BB / 64, (T + 127) / 128);
    fir_kernel<<<gA, 128>>>(currents, a, b_act, max_cur, T);

    rec_kernel2<<<BB / 16, 128>>>(b_lag, poly, max_cur, max_fr, T);

    dim3 gC(BB / 32, (T + 31) / 32);
    tr_kernel<<<gC, dim3(32, 8)>>>(out, max_fr, T);
}